// round 17
// baseline (speedup 1.0000x reference)
#include <cuda_runtime.h>
#include <math.h>

#define Lr 1024
#define Br 32
#define Dr 256
#define LAMf 0.2f
#define NR (Lr*Br)

// Scratch (device globals, zero-initialized). Batch-major r = b*Lr + i.
// Rows >= l are never written and stay 0 (graph-replay deterministic).
__device__ float g_Kn[NR*5];     // K[i,d] * invS[i]
__device__ float g_En[NR];       // E[i]  * invS[i]
__device__ int   g_cnt[Br];      // per-batch arrival counters (reset by epilogue)

typedef unsigned long long u64;

__device__ __forceinline__ u64 ffma2(u64 a, u64 b, u64 c) {
    u64 d;
    asm("fma.rn.f32x2 %0, %1, %2, %3;" : "=l"(d) : "l"(a), "l"(b), "l"(c));
    return d;
}
__device__ __forceinline__ float unpack_sum(u64 a) {
    float2 f = *reinterpret_cast<float2*>(&a);
    return f.x + f.y;
}

// Single kernel: 2048 band blocks (R14 math) + 32 epilogue blocks (last wave).
__global__ void __launch_bounds__(512) kall(const float* __restrict__ m1,
                                            const float* __restrict__ m2,
                                            const int* __restrict__ lengths,
                                            float* __restrict__ out) {
    __shared__ __align__(16) float sh_Kn[16*5];   // band: per-row results
    __shared__ __align__(16) float sh_En[16];
    __shared__ float sh_invny[20];
    __shared__ float sh_t[Lr];                    // epilogue (4 KB)
    __shared__ float sh_c[512];

    int tid = threadIdx.x;
    int bid = blockIdx.x;

    if (bid < 2048) {
        // ======================= BAND BLOCK (R14 math) =======================
        int w    = tid >> 5, lane = tid & 31;
        int b    = bid & 31;
        int i0   = (bid >> 5) * 16;
        int l    = __ldg(lengths + b);
        int base = b * Lr;
        int i    = i0 + w;

        // zero result slots (rows >= l keep zeros)
        if (tid < 80) sh_Kn[tid] = 0.0f;
        if (tid < 16) sh_En[tid] = 0.0f;

        // main: x load + 5 dots + xx + yy(d=2), one 7-wide butterfly
        float s[7];
        if (i < l) {
            const ulonglong2* xp = (const ulonglong2*)(m1 + ((size_t)(i*Br + b)) * Dr);
            ulonglong2 xa = xp[lane], xb = xp[lane + 32];
            u64 pacc[7];
            pacc[0] = ffma2(xa.x, xa.x, 0ull);
            pacc[0] = ffma2(xa.y, xa.y, pacc[0]);
            pacc[0] = ffma2(xb.x, xb.x, pacc[0]);
            pacc[0] = ffma2(xb.y, xb.y, pacc[0]);
            pacc[6] = 0ull;
            #pragma unroll
            for (int d = 0; d < 5; d++) {
                int j = i + d - 2;
                u64 acc = 0ull;
                if (j >= 0 && j < l) {
                    const ulonglong2* yp = (const ulonglong2*)(m2 + ((size_t)(j*Br + b)) * Dr);
                    ulonglong2 ya = yp[lane], yb = yp[lane + 32];
                    acc = ffma2(xa.x, ya.x, acc);
                    acc = ffma2(xa.y, ya.y, acc);
                    acc = ffma2(xb.x, yb.x, acc);
                    acc = ffma2(xb.y, yb.y, acc);
                    if (d == 2) {
                        u64 yy = ffma2(ya.x, ya.x, 0ull);
                        yy = ffma2(ya.y, ya.y, yy);
                        yy = ffma2(yb.x, yb.x, yy);
                        yy = ffma2(yb.y, yb.y, yy);
                        pacc[6] = yy;
                    }
                }
                pacc[d + 1] = acc;
            }
            #pragma unroll
            for (int q = 0; q < 7; q++) s[q] = unpack_sum(pacc[q]);
            #pragma unroll
            for (int o = 16; o; o >>= 1) {
                #pragma unroll
                for (int q = 0; q < 7; q++) s[q] += __shfl_xor_sync(0xffffffffu, s[q], o);
            }
            if (lane == 0)
                sh_invny[w + 2] = 1.0f / fmaxf(sqrtf(s[6]), 1e-5f);
        }

        // mini-pass: 4 edge y-norm rows by warps 0-3
        if (w < 4) {
            int eidx = (w < 2) ? w : (16 + w);
            int row  = i0 - 2 + eidx;
            float ss = 0.0f;
            if (row >= 0 && row < l) {
                const ulonglong2* p = (const ulonglong2*)(m2 + ((size_t)(row*Br + b)) * Dr);
                ulonglong2 a = p[lane], c = p[lane + 32];
                u64 q = ffma2(a.x, a.x, 0ull);
                q = ffma2(a.y, a.y, q);
                q = ffma2(c.x, c.x, q);
                q = ffma2(c.y, c.y, q);
                ss = unpack_sum(q);
            }
            #pragma unroll
            for (int o = 16; o; o >>= 1) ss += __shfl_xor_sync(0xffffffffu, ss, o);
            if (lane == 0)
                sh_invny[eidx] = (ss > 0.0f) ? (1.0f / fmaxf(sqrtf(ss), 1e-5f)) : 0.0f;
        }
        __syncthreads();

        // lane-parallel tail -> smem
        if (i < l) {
            float invnx = 1.0f / fmaxf(sqrtf(s[0]), 1e-5f);
            int d = lane;
            float Kv = 0.0f, Ev = 0.0f;
            if (d < 5) {
                int j = i + d - 2;
                if (j >= 0 && j < l) {
                    float Mv = 1.0f - s[d + 1] * invnx * sh_invny[w + d];
                    Kv = __expf(-LAMf * Mv);
                    Ev = Kv * Mv;
                }
            }
            float S = Kv, E = Ev;
            #pragma unroll
            for (int o = 4; o; o >>= 1) {
                S += __shfl_xor_sync(0xffffffffu, S, o);
                E += __shfl_xor_sync(0xffffffffu, E, o);
            }
            float invS = 1.0f / S;
            if (lane < 5) sh_Kn[w*5 + lane] = Kv * invS;
            if (lane == 0) sh_En[w] = E * invS;
        }
        __syncthreads();

        // coalesced copy-out (24 threads), single predicated MEMBAR, one atomic
        if (tid < 20)
            ((float4*)(g_Kn + (size_t)(base + i0) * 5))[tid] = ((const float4*)sh_Kn)[tid];
        else if (tid < 24)
            ((float4*)(g_En + base + i0))[tid - 20] = ((const float4*)sh_En)[tid - 20];
        if (tid < 24) __threadfence();          // one MEMBAR instruction (warp 0)
        __syncthreads();
        if (tid == 0) atomicAdd(&g_cnt[b], 1);
        return;
    }

    // ======================= EPILOGUE BLOCK (batch b) =======================
    int b = bid - 2048;
    int l = __ldg(lengths + b);
    int base = b * Lr;

    if (tid == 0) {
        volatile int* cnt = (volatile int*)&g_cnt[b];
        while (*cnt != 64) __nanosleep(128);
        g_cnt[b] = 0;                           // reset for next graph replay
        __threadfence();
    }
    __syncthreads();

    // t[j] for rows tid, tid+512 via scattered L2 reads
    #pragma unroll
    for (int half = 0; half < 2; half++) {
        int j = tid + half*512;
        float t = 1.0f;
        if (j < l) {
            t = 0.0f;
            #pragma unroll
            for (int dd = 0; dd < 5; dd++) {
                int i = j + dd - 2;
                if (i >= 0 && i < l)
                    t += __ldcg(g_Kn + (size_t)(base + i)*5 + (4 - dd));
            }
        }
        sh_t[j] = t;
    }
    __syncthreads();

    // band scatter + cost terms
    float acc = 0.0f;
    #pragma unroll
    for (int half = 0; half < 2; half++) {
        int j = tid + half*512;
        if (j < l) {
            float rt = 1.0f / sh_t[j];
            acc += __ldcg(g_En + base + j) * rt / (float)l;
            float* Po = out + (size_t)b * Lr * Lr + (size_t)j * Lr;
            #pragma unroll
            for (int d = 0; d < 5; d++) {
                int jj = j + d - 2;
                if (jj >= 0 && jj < l)
                    Po[jj] = __ldcg(g_Kn + (size_t)(base + j)*5 + d) * sh_t[jj] * rt;
            }
        }
    }

    sh_c[tid] = acc;
    __syncthreads();
    #pragma unroll
    for (int s = 256; s; s >>= 1) {
        if (tid < s) sh_c[tid] += sh_c[tid + s];
        __syncthreads();
    }
    if (tid == 0) out[(size_t)Br * Lr * Lr + b] = sh_c[0];
}

extern "C" void kernel_launch(void* const* d_in, const int* in_sizes, int n_in,
                              void* d_out, int out_size) {
    const float* m1      = (const float*)d_in[0];
    const float* m2      = (const float*)d_in[1];
    const int*   lengths = (const int*)d_in[2];
    float* out = (float*)d_out;

    kall<<<2048 + Br, 512>>>(m1, m2, lengths, out);   // one launch: band + lean epilogue
}